// round 5
// baseline (speedup 1.0000x reference)
#include <cuda_runtime.h>
#include <cuda_bf16.h>
#include <cstdint>

#define DDIM 512
#define KDIM 512
#define BM   64
#define BK   32
#define NTH  512
#define NCH  16

// static scratch (no allocations allowed)
__device__ __nv_bfloat16 g_cb[KDIM * DDIM];  // clusters bf16 [K][D]
__device__ float g_c2[KDIM];

// ---- smem layout (bytes) ----
#define ASTRIDE 80            // 32 bf16 = 64B payload, 80B stride (conflict-free ldmatrix)
#define ACHUNK  (BM * ASTRIDE)        // 5120 per K-chunk
#define BSTAGEB (KDIM * ASTRIDE)      // 40960 per stage
#define OFF_A   0u                    // 16 * 5120 = 81920  (A resident, all chunks)
#define OFF_B   81920u                // 3 * 40960 = 122880 -> 204800
#define OFF_C2  204800u               // 512*4  -> 206848
#define OFF_X2  206848u               // 64*4   -> 207104
#define OFF_RS  207104u               // 8*64*4 -> 209152
#define SMEM_TOTAL 209152u

// ---------------- helpers ----------------
__device__ __forceinline__ float frcp(float a) {
    float r; asm("rcp.approx.ftz.f32 %0, %1;" : "=f"(r) : "f"(a)); return r;
}
__device__ __forceinline__ uint32_t pk(float a, float b) {
    __nv_bfloat162 h = __floats2bfloat162_rn(a, b);
    return *reinterpret_cast<uint32_t*>(&h);
}
__device__ __forceinline__ void cp16(uint32_t dst, const void* src) {
    asm volatile("cp.async.cg.shared.global [%0], [%1], 16;"
                 :: "r"(dst), "l"(__cvta_generic_to_global(src)) : "memory");
}
#define CP_COMMIT() asm volatile("cp.async.commit_group;" ::: "memory")
template <int N>
__device__ __forceinline__ void cp_wait() {
    asm volatile("cp.async.wait_group %0;" :: "n"(N) : "memory");
}
__device__ __forceinline__ void ldsm4(uint32_t* r, uint32_t a) {
    asm volatile("ldmatrix.sync.aligned.m8n8.x4.shared.b16 {%0,%1,%2,%3}, [%4];"
                 : "=r"(r[0]), "=r"(r[1]), "=r"(r[2]), "=r"(r[3]) : "r"(a));
}
__device__ __forceinline__ void mma16816(float* c, const uint32_t* a, uint32_t b0, uint32_t b1) {
    asm volatile("mma.sync.aligned.m16n8k16.row.col.f32.bf16.bf16.f32 "
                 "{%0,%1,%2,%3}, {%4,%5,%6,%7}, {%8,%9}, {%0,%1,%2,%3};"
                 : "+f"(c[0]), "+f"(c[1]), "+f"(c[2]), "+f"(c[3])
                 : "r"(a[0]), "r"(a[1]), "r"(a[2]), "r"(a[3]), "r"(b0), "r"(b1));
}

// ---------------- prep: clusters -> bf16, c2 fp32 (tiny: ~3us) ----------------
__global__ void prep_kernel(const float* __restrict__ clusters) {
    int k = blockIdx.x, tid = threadIdx.x;
    const float* row = clusters + (size_t)k * DDIM;
    float s = 0.f;
    for (int d = tid; d < DDIM; d += 128) {
        float v = row[d];
        s += v * v;
        g_cb[(size_t)k * DDIM + d] = __float2bfloat16(v);
    }
    #pragma unroll
    for (int o = 16; o > 0; o >>= 1) s += __shfl_xor_sync(0xffffffffu, s, o);
    __shared__ float red[4];
    if ((tid & 31) == 0) red[tid >> 5] = s;
    __syncthreads();
    if (tid == 0) g_c2[k] = red[0] + red[1] + red[2] + red[3];
}

// ---------------- main fused kernel ----------------
// CTA: 64 rows x all 512 cols. Warp grid 2(M) x 8(N); warp tile 32x64.
// A (64x512 bf16) converted once into smem; B streamed 3-stage via cp.async.
__global__ void __launch_bounds__(NTH, 1)
cluster_kernel(const float* __restrict__ x, float* __restrict__ out) {
    extern __shared__ char smem[];
    char*  smA = smem + OFF_A;
    char*  smB = smem + OFF_B;
    float* c2s = (float*)(smem + OFF_C2);
    float* x2s = (float*)(smem + OFF_X2);
    float* rss = (float*)(smem + OFF_RS);

    const int tid = threadIdx.x, lane = tid & 31, wid = tid >> 5;
    const int wm = wid & 1, wn = wid >> 1;          // 2 x 8 warp grid
    const long row0 = (long)blockIdx.x * BM;
    const float* xblk = x + row0 * DDIM;

    const uint32_t sA = (uint32_t)__cvta_generic_to_shared(smA);
    const uint32_t sB = (uint32_t)__cvta_generic_to_shared(smB);

    // B loader: chunk c (cols [c*32, c*32+32) of all 512 cluster rows), 32KB
    auto loadB = [&](int c, int s) {
        #pragma unroll
        for (int i = 0; i < 4; i++) {
            int idx = tid + i * NTH;
            int brow = idx >> 2, seg = idx & 3;
            uint32_t dst = sB + s * BSTAGEB + brow * ASTRIDE + seg * 16;
            const char* src = (const char*)g_cb + (size_t)brow * (DDIM * 2)
                              + c * (BK * 2) + seg * 16;
            cp16(dst, src);
        }
        CP_COMMIT();
    };

    // prefetch B chunks 0,1 first so they land while we convert A
    loadB(0, 0);
    loadB(1, 1);

    for (int i = tid; i < KDIM; i += NTH) c2s[i] = g_c2[i];

    // ---- A: convert x tile fp32 -> bf16 into chunked smem layout, + ||x||^2 ----
    {
        const int arow = tid >> 3, a8 = tid & 7;   // 8 threads per row, 64 floats each
        const float4* src = (const float4*)(xblk + (size_t)arow * DDIM + a8 * 64);
        float x2a = 0.f;
        #pragma unroll
        for (int j = 0; j < 8; j++) {
            float4 u = src[2 * j], v = src[2 * j + 1];
            x2a += u.x * u.x + u.y * u.y + u.z * u.z + u.w * u.w;
            x2a += v.x * v.x + v.y * v.y + v.z * v.z + v.w * v.w;
            uint4 w = make_uint4(pk(u.x, u.y), pk(u.z, u.w), pk(v.x, v.y), pk(v.z, v.w));
            int col = a8 * 64 + j * 8;            // fp32 col index
            int ch = col >> 5, cc = col & 31;     // chunk, col-in-chunk
            *(uint4*)(smA + ch * ACHUNK + arow * ASTRIDE + cc * 2) = w;
        }
        x2a += __shfl_xor_sync(0xffffffffu, x2a, 1);
        x2a += __shfl_xor_sync(0xffffffffu, x2a, 2);
        x2a += __shfl_xor_sync(0xffffffffu, x2a, 4);
        if ((lane & 7) == 0) x2s[arow] = x2a;
    }
    // (first loop iteration's __syncthreads makes A + x2 + c2 visible)

    float acc[2][8][4];
    #pragma unroll
    for (int mt = 0; mt < 2; mt++)
        #pragma unroll
        for (int nt = 0; nt < 8; nt++)
            #pragma unroll
            for (int j = 0; j < 4; j++) acc[mt][nt][j] = 0.f;

    const uint32_t lmr = lane & 15, lmc = (lane >> 4) * 16;

    // ---- mainloop: 16 K-chunks, 3-stage B, A resident ----
    #pragma unroll
    for (int c = 0; c < NCH; c++) {
        if (c == NCH - 1) cp_wait<0>(); else cp_wait<1>();
        __syncthreads();
        if (c + 2 < NCH) loadB(c + 2, (c + 2) % 3);

        const uint32_t abase = sA + c * ACHUNK + lmc;
        const uint32_t bbase = sB + (c % 3) * BSTAGEB + lmc;
        #pragma unroll
        for (int ks = 0; ks < 2; ks++) {
            uint32_t a0[4], a1[4];
            ldsm4(a0, abase + ks * 32 + (wm * 32 + 0  + lmr) * ASTRIDE);
            ldsm4(a1, abase + ks * 32 + (wm * 32 + 16 + lmr) * ASTRIDE);
            #pragma unroll
            for (int bt = 0; bt < 4; bt++) {
                uint32_t b[4];
                ldsm4(b, bbase + ks * 32 + (wn * 64 + bt * 16 + lmr) * ASTRIDE);
                mma16816(acc[0][2 * bt + 0], a0, b[0], b[2]);
                mma16816(acc[0][2 * bt + 1], a0, b[1], b[3]);
                mma16816(acc[1][2 * bt + 0], a1, b[0], b[2]);
                mma16816(acc[1][2 * bt + 1], a1, b[1], b[3]);
            }
        }
    }

    // ---- epilogue: d2 -> q, row sums, normalize, store ----
    #pragma unroll
    for (int mt = 0; mt < 2; mt++) {
        #pragma unroll
        for (int rr = 0; rr < 2; rr++) {
            const int row = wm * 32 + mt * 16 + (lane >> 2) + rr * 8;
            const float x2v = x2s[row];
            float rsum = 0.f;
            #pragma unroll
            for (int nt = 0; nt < 8; nt++) {
                const int col = wn * 64 + nt * 8 + (lane & 3) * 2;
                float d0 = fmaxf(fmaf(-2.f, acc[mt][nt][rr * 2 + 0], x2v + c2s[col]), 0.f);
                float d1 = fmaxf(fmaf(-2.f, acc[mt][nt][rr * 2 + 1], x2v + c2s[col + 1]), 0.f);
                float q0 = frcp(1.f + d0), q1 = frcp(1.f + d1);
                acc[mt][nt][rr * 2 + 0] = q0;
                acc[mt][nt][rr * 2 + 1] = q1;
                rsum += q0 + q1;
            }
            rsum += __shfl_xor_sync(0xffffffffu, rsum, 1);
            rsum += __shfl_xor_sync(0xffffffffu, rsum, 2);
            if ((lane & 3) == 0) rss[wn * 64 + row] = rsum;
        }
    }
    __syncthreads();

    #pragma unroll
    for (int mt = 0; mt < 2; mt++) {
        #pragma unroll
        for (int rr = 0; rr < 2; rr++) {
            const int row = wm * 32 + mt * 16 + (lane >> 2) + rr * 8;
            float s = 0.f;
            #pragma unroll
            for (int w = 0; w < 8; w++) s += rss[w * 64 + row];
            const float inv = frcp(s);
            float* orow = out + (row0 + row) * KDIM;
            #pragma unroll
            for (int nt = 0; nt < 8; nt++) {
                const int col = wn * 64 + nt * 8 + (lane & 3) * 2;
                *(float2*)&orow[col] = make_float2(acc[mt][nt][rr * 2 + 0] * inv,
                                                   acc[mt][nt][rr * 2 + 1] * inv);
            }
        }
    }
}

extern "C" void kernel_launch(void* const* d_in, const int* in_sizes, int n_in,
                              void* d_out, int out_size) {
    const float* x        = (const float*)d_in[0];
    const float* clusters = (const float*)d_in[1];
    float* out = (float*)d_out;
    int n = in_sizes[0] / DDIM;   // 131072

    cudaFuncSetAttribute(cluster_kernel, cudaFuncAttributeMaxDynamicSharedMemorySize, SMEM_TOTAL);
    prep_kernel<<<KDIM, 128>>>(clusters);
    cluster_kernel<<<n / BM, NTH, SMEM_TOTAL>>>(x, out);
}

// round 6
// speedup vs baseline: 1.2354x; 1.2354x over previous
#include <cuda_runtime.h>
#include <cuda_fp16.h>
#include <cstdint>

#define DDIM 512
#define KDIM 512
#define BM   128
#define BK   32
#define NTH  512
#define NCH  16

// static scratch (no allocations allowed)
__device__ __half g_cb[KDIM * DDIM];   // clusters fp16 [K][D]
__device__ float g_c2[KDIM];

// ---- smem layout (bytes) ----
#define BSTRIDE 80                    // B rows: 64B payload, 80B stride (conflict-free ldsm)
#define BSTAGEB (KDIM * BSTRIDE)      // 40960 per stage
#define OFF_A   0u                    // 128 rows * 1024B (swizzled) = 131072, resident
#define OFF_B   131072u               // 2 * 40960 -> 212992
#define OFF_C2  212992u               // 512*4  -> 215040
#define OFF_X2  215040u               // 128*4  -> 215552
#define OFF_RS  215552u               // 4*128*4 -> 217600
#define SMEM_TOTAL 217600u

// ---------------- helpers ----------------
__device__ __forceinline__ float frcp(float a) {
    float r; asm("rcp.approx.ftz.f32 %0, %1;" : "=f"(r) : "f"(a)); return r;
}
__device__ __forceinline__ uint32_t pkh(float a, float b) {
    __half2 h = __floats2half2_rn(a, b);
    return *reinterpret_cast<uint32_t*>(&h);
}
// A swizzle: row r (0..127) x byte-col cb (0..1023); XOR bits[4:6] with row%8
__device__ __forceinline__ uint32_t asw(uint32_t r, uint32_t cb) {
    return r * 1024u + (cb ^ ((r & 7u) << 4));
}
__device__ __forceinline__ void cp16(uint32_t dst, const void* src) {
    asm volatile("cp.async.cg.shared.global [%0], [%1], 16;"
                 :: "r"(dst), "l"(__cvta_generic_to_global(src)) : "memory");
}
#define CP_COMMIT() asm volatile("cp.async.commit_group;" ::: "memory")
template <int N>
__device__ __forceinline__ void cp_wait() {
    asm volatile("cp.async.wait_group %0;" :: "n"(N) : "memory");
}
__device__ __forceinline__ void ldsm4(uint32_t* r, uint32_t a) {
    asm volatile("ldmatrix.sync.aligned.m8n8.x4.shared.b16 {%0,%1,%2,%3}, [%4];"
                 : "=r"(r[0]), "=r"(r[1]), "=r"(r[2]), "=r"(r[3]) : "r"(a));
}
// fp16-accumulator HMMA: D,C = {2 x b32} = 4 halves
__device__ __forceinline__ void mma_f16(uint32_t* c, const uint32_t* a, uint32_t b0, uint32_t b1) {
    asm volatile("mma.sync.aligned.m16n8k16.row.col.f16.f16.f16.f16 "
                 "{%0,%1}, {%2,%3,%4,%5}, {%6,%7}, {%0,%1};"
                 : "+r"(c[0]), "+r"(c[1])
                 : "r"(a[0]), "r"(a[1]), "r"(a[2]), "r"(a[3]), "r"(b0), "r"(b1));
}

// ---------------- prep: clusters -> fp16, c2 fp32 ----------------
__global__ void prep_kernel(const float* __restrict__ clusters) {
    int k = blockIdx.x, tid = threadIdx.x;
    const float* row = clusters + (size_t)k * DDIM;
    float s = 0.f;
    for (int d = tid; d < DDIM; d += 128) {
        float v = row[d];
        s += v * v;
        g_cb[(size_t)k * DDIM + d] = __float2half(v);
    }
    #pragma unroll
    for (int o = 16; o > 0; o >>= 1) s += __shfl_xor_sync(0xffffffffu, s, o);
    __shared__ float red[4];
    if ((tid & 31) == 0) red[tid >> 5] = s;
    __syncthreads();
    if (tid == 0) g_c2[k] = red[0] + red[1] + red[2] + red[3];
}

// ---------------- main fused kernel ----------------
// CTA: 128 rows x all 512 cols, one pass. Warp grid 4(M) x 4(N); warp tile 32x128.
// fp16 accumulators (2 values/reg). A resident in smem; B streamed 2-stage cp.async.
__global__ void __launch_bounds__(NTH, 1)
cluster_kernel(const float* __restrict__ x, float* __restrict__ out) {
    extern __shared__ char smem[];
    char*  smA = smem + OFF_A;
    char*  smB = smem + OFF_B;
    float* c2s = (float*)(smem + OFF_C2);
    float* x2s = (float*)(smem + OFF_X2);
    float* rss = (float*)(smem + OFF_RS);

    const int tid = threadIdx.x, lane = tid & 31, wid = tid >> 5;
    const int wm = wid & 3, wn = wid >> 2;          // 4 x 4 warp grid
    const long row0 = (long)blockIdx.x * BM;
    const float* xblk = x + row0 * DDIM;

    const uint32_t sA = (uint32_t)__cvta_generic_to_shared(smA);
    const uint32_t sB = (uint32_t)__cvta_generic_to_shared(smB);

    // B loader: chunk c = cols [c*32, c*32+32) of all 512 cluster rows (32 KB)
    auto loadB = [&](int c, int s) {
        #pragma unroll
        for (int i = 0; i < 4; i++) {
            int idx = tid + i * NTH;
            int brow = idx >> 2, seg = idx & 3;
            uint32_t dst = sB + s * BSTAGEB + brow * BSTRIDE + seg * 16;
            const char* src = (const char*)g_cb + (size_t)brow * (DDIM * 2)
                              + c * (BK * 2) + seg * 16;
            cp16(dst, src);
        }
        CP_COMMIT();
    };

    loadB(0, 0);   // prefetch chunk 0 while we convert A

    for (int i = tid; i < KDIM; i += NTH) c2s[i] = g_c2[i];

    // ---- A: convert x tile fp32 -> fp16 into swizzled resident smem, + ||x||^2 ----
    {
        const int arow = tid >> 2, aq = tid & 3;    // 4 threads per row
        const float* src = xblk + (size_t)arow * DDIM;
        float x2a = 0.f;
        #pragma unroll
        for (int j = 0; j < 16; j++) {
            const int fc = aq * 8 + j * 32;         // float col
            float4 u = *(const float4*)(src + fc);
            float4 v = *(const float4*)(src + fc + 4);
            x2a += u.x * u.x + u.y * u.y + u.z * u.z + u.w * u.w;
            x2a += v.x * v.x + v.y * v.y + v.z * v.z + v.w * v.w;
            uint4 w = make_uint4(pkh(u.x, u.y), pkh(u.z, u.w), pkh(v.x, v.y), pkh(v.z, v.w));
            *(uint4*)(smA + asw(arow, fc * 2)) = w;
        }
        x2a += __shfl_xor_sync(0xffffffffu, x2a, 1);
        x2a += __shfl_xor_sync(0xffffffffu, x2a, 2);
        if ((lane & 3) == 0) x2s[arow] = x2a;
    }

    uint32_t acc[2][16][2];
    #pragma unroll
    for (int mt = 0; mt < 2; mt++)
        #pragma unroll
        for (int nt = 0; nt < 16; nt++) { acc[mt][nt][0] = 0u; acc[mt][nt][1] = 0u; }

    const uint32_t lmr = lane & 15, lmc = (lane >> 4) * 16;
    const uint32_t xr  = ((wm * 32 + lmr) & 7u) << 4;          // (r+16)&7 == r&7
    const uint32_t aro0 = (uint32_t)(wm * 32 + lmr) * 1024u;
    const uint32_t aro1 = (uint32_t)(wm * 32 + 16 + lmr) * 1024u;

    // ---- mainloop: 16 K-chunks, A resident, B double-buffered ----
    #pragma unroll 1
    for (int c = 0; c < NCH; c++) {
        cp_wait<0>();
        __syncthreads();                       // chunk c visible; stage (c+1)&1 free
        if (c + 1 < NCH) loadB(c + 1, (c + 1) & 1);

        const uint32_t bbase = sB + (c & 1) * BSTAGEB + lmc;
        #pragma unroll
        for (int ks = 0; ks < 2; ks++) {
            const uint32_t acb = ((uint32_t)(c * 64 + ks * 32) + lmc) ^ xr;
            uint32_t a0[4], a1[4];
            ldsm4(a0, sA + aro0 + acb);
            ldsm4(a1, sA + aro1 + acb);
            #pragma unroll
            for (int bt = 0; bt < 8; bt++) {
                uint32_t b[4];
                ldsm4(b, bbase + ks * 32 + (wn * 128 + bt * 16 + lmr) * BSTRIDE);
                mma_f16(acc[0][2 * bt + 0], a0, b[0], b[2]);
                mma_f16(acc[0][2 * bt + 1], a0, b[1], b[3]);
                mma_f16(acc[1][2 * bt + 0], a1, b[0], b[2]);
                mma_f16(acc[1][2 * bt + 1], a1, b[1], b[3]);
            }
        }
    }

    // ---- epilogue pass 1: row sums (q recomputed later; nothing stored) ----
    #pragma unroll
    for (int mt = 0; mt < 2; mt++) {
        #pragma unroll
        for (int rr = 0; rr < 2; rr++) {
            const int row = wm * 32 + mt * 16 + (lane >> 2) + rr * 8;
            const float x2v = x2s[row];
            float rsum = 0.f;
            #pragma unroll
            for (int nt = 0; nt < 16; nt++) {
                float2 f = __half22float2(*(__half2*)&acc[mt][nt][rr]);
                const int col = wn * 128 + nt * 8 + (lane & 3) * 2;
                float d0 = fmaxf(fmaf(-2.f, f.x, x2v + c2s[col]), 0.f);
                float d1 = fmaxf(fmaf(-2.f, f.y, x2v + c2s[col + 1]), 0.f);
                rsum += frcp(1.f + d0) + frcp(1.f + d1);
            }
            rsum += __shfl_xor_sync(0xffffffffu, rsum, 1);
            rsum += __shfl_xor_sync(0xffffffffu, rsum, 2);
            if ((lane & 3) == 0) rss[wn * 128 + row] = rsum;
        }
    }
    __syncthreads();

    // ---- epilogue pass 2: normalize (recompute q in fp32) and store ----
    #pragma unroll
    for (int mt = 0; mt < 2; mt++) {
        #pragma unroll
        for (int rr = 0; rr < 2; rr++) {
            const int row = wm * 32 + mt * 16 + (lane >> 2) + rr * 8;
            const float x2v = x2s[row];
            const float inv = frcp(rss[row] + rss[128 + row] + rss[256 + row] + rss[384 + row]);
            float* orow = out + (row0 + row) * KDIM;
            #pragma unroll
            for (int nt = 0; nt < 16; nt++) {
                float2 f = __half22float2(*(__half2*)&acc[mt][nt][rr]);
                const int col = wn * 128 + nt * 8 + (lane & 3) * 2;
                float d0 = fmaxf(fmaf(-2.f, f.x, x2v + c2s[col]), 0.f);
                float d1 = fmaxf(fmaf(-2.f, f.y, x2v + c2s[col + 1]), 0.f);
                *(float2*)&orow[col] = make_float2(frcp(1.f + d0) * inv, frcp(1.f + d1) * inv);
            }
        }
    }
}

extern "C" void kernel_launch(void* const* d_in, const int* in_sizes, int n_in,
                              void* d_out, int out_size) {
    const float* x        = (const float*)d_in[0];
    const float* clusters = (const float*)d_in[1];
    float* out = (float*)d_out;
    int n = in_sizes[0] / DDIM;   // 131072

    cudaFuncSetAttribute(cluster_kernel, cudaFuncAttributeMaxDynamicSharedMemorySize, SMEM_TOTAL);
    prep_kernel<<<KDIM, 128>>>(clusters);
    cluster_kernel<<<n / BM, NTH, SMEM_TOTAL>>>(x, out);
}